// round 1
// baseline (speedup 1.0000x reference)
#include <cuda_runtime.h>
#include <math.h>

#define BB 64
#define TT 512
#define NKEY 512
#define DD 256

// Scratch (device globals: allocation-free per harness rules)
__device__ float g_x[BB*TT*DD];
__device__ float g_q[BB*TT*DD];
__device__ float g_k[BB*NKEY*DD];
__device__ float g_v[BB*NKEY*DD];
__device__ float g_pmax[BB*8*DD];

// ---------------------------------------------------------------------------
// K1: x = leaky_relu(LN(traj @ w_mlp + b_mlp)) + emb[labels]   -> g_x [B,T,D]
// one block per (b,t) row, 256 threads (one per d)
// ---------------------------------------------------------------------------
__global__ void k_build_x(const float* __restrict__ traj, const int* __restrict__ labels,
                          const float* __restrict__ emb, const float* __restrict__ w_mlp,
                          const float* __restrict__ b_mlp, const float* __restrict__ ln_g,
                          const float* __restrict__ ln_b) {
    int b = blockIdx.y, t = blockIdx.x, d = threadIdx.x;
    int row = b*TT + t;
    float t0 = traj[row*2 + 0];
    float t1 = traj[row*2 + 1];
    float v = t0*w_mlp[d] + t1*w_mlp[DD + d] + b_mlp[d];

    // block reduce sum & sumsq
    float s = v, s2 = v*v;
    #pragma unroll
    for (int o = 16; o; o >>= 1) {
        s  += __shfl_down_sync(0xFFFFFFFFu, s,  o);
        s2 += __shfl_down_sync(0xFFFFFFFFu, s2, o);
    }
    __shared__ float ws[8], ws2[8];
    __shared__ float smu, srs;
    int lane = d & 31, w = d >> 5;
    if (lane == 0) { ws[w] = s; ws2[w] = s2; }
    __syncthreads();
    if (d == 0) {
        float a = 0.f, a2 = 0.f;
        #pragma unroll
        for (int i = 0; i < 8; i++) { a += ws[i]; a2 += ws2[i]; }
        float mu  = a  * (1.f/DD);
        float var = a2 * (1.f/DD) - mu*mu;
        smu = mu;
        srs = rsqrtf(var + 1e-5f);
    }
    __syncthreads();
    float y = (v - smu) * srs * ln_g[d] + ln_b[d];
    y = (y >= 0.f) ? y : 0.01f * y;            // leaky_relu slope 0.01
    y += emb[labels[b]*DD + d];
    g_x[row*DD + d] = y;
}

// ---------------------------------------------------------------------------
// K2: q = x@wq+bq ; k = h@wk+bk ; v = h@wv+bv    (blockIdx.z selects)
// SGEMM: BM=128, BN=128, BK=16, 256 threads, 8x8 microtile
// ---------------------------------------------------------------------------
__global__ __launch_bounds__(256) void k_qkv(const float* __restrict__ h,
        const float* __restrict__ wq, const float* __restrict__ bq,
        const float* __restrict__ wk, const float* __restrict__ bk,
        const float* __restrict__ wv, const float* __restrict__ bv) {
    const float *A, *W, *bias;
    float *Out;
    if      (blockIdx.z == 0) { A = g_x; W = wq; bias = bq; Out = g_q; }
    else if (blockIdx.z == 1) { A = h;   W = wk; bias = bk; Out = g_k; }
    else                      { A = h;   W = wv; bias = bv; Out = g_v; }

    __shared__ float As[16*130];   // transposed [k][m], stride 130 (conflict-free)
    __shared__ float Bs[16*128];   // [k][n]

    int tid = threadIdx.x;
    int tx = tid & 15, ty = tid >> 4;
    int m0 = blockIdx.x * 128, n0 = blockIdx.y * 128;

    float acc[8][8];
    #pragma unroll
    for (int j = 0; j < 8; j++)
        #pragma unroll
        for (int i = 0; i < 8; i++) acc[j][i] = 0.f;

    for (int k0 = 0; k0 < 256; k0 += 16) {
        // load A tile 128x16 (transposed into smem)
        #pragma unroll
        for (int sld = 0; sld < 2; sld++) {
            int f = tid + sld*256;             // 0..511 float4 slots
            int r = f >> 2, kc = (f & 3) * 4;
            float4 av = *(const float4*)&A[(m0 + r)*256 + k0 + kc];
            As[(kc+0)*130 + r] = av.x;
            As[(kc+1)*130 + r] = av.y;
            As[(kc+2)*130 + r] = av.z;
            As[(kc+3)*130 + r] = av.w;
        }
        // load B tile 16x128
        #pragma unroll
        for (int sld = 0; sld < 2; sld++) {
            int f = tid + sld*256;
            int kr = f >> 5, c4 = (f & 31) * 4;
            *(float4*)&Bs[kr*128 + c4] = *(const float4*)&W[(k0+kr)*256 + n0 + c4];
        }
        __syncthreads();
        #pragma unroll
        for (int kk = 0; kk < 16; kk++) {
            float a[8], bb[8];
            #pragma unroll
            for (int j = 0; j < 8; j++) a[j] = As[kk*130 + ty*8 + j];
            #pragma unroll
            for (int i = 0; i < 8; i++) bb[i] = Bs[kk*128 + i*16 + tx];
            #pragma unroll
            for (int j = 0; j < 8; j++)
                #pragma unroll
                for (int i = 0; i < 8; i++)
                    acc[j][i] += a[j]*bb[i];
        }
        __syncthreads();
    }
    #pragma unroll
    for (int j = 0; j < 8; j++) {
        int m = m0 + ty*8 + j;
        #pragma unroll
        for (int i = 0; i < 8; i++) {
            int n = n0 + i*16 + tx;
            Out[m*256 + n] = acc[j][i] + bias[n];
        }
    }
}

// ---------------------------------------------------------------------------
// K3: flash attention + fused per-tile max pool.
// Grid (8 t-tiles, 64 batches), 256 threads. 64 t-rows per block.
// Skips key tiles beyond valid_len; masks within the boundary tile.
// ---------------------------------------------------------------------------
#define QS_STRIDE 257
#define SS_STRIDE 65
#define ATTN_SMEM ((2*64*QS_STRIDE + 64*SS_STRIDE + 3*64) * 4)

__global__ __launch_bounds__(256) void k_attn(const int* __restrict__ valid_len) {
    extern __shared__ float smbuf[];
    float* Qs   = smbuf;                       // 64 x 257
    float* KV   = Qs + 64*QS_STRIDE;           // 64 x 257 (K, then reused for V)
    float* Ss   = KV + 64*QS_STRIDE;           // 64 x 65  (scores/P; reused 16x256 for reduce)
    float* mrow = Ss + 64*SS_STRIDE;           // 64
    float* lrow = mrow + 64;                   // 64
    float* crow = lrow + 64;                   // 64

    int tid = threadIdx.x;
    int tx = tid & 15, ty = tid >> 4;
    int b = blockIdx.y, ttile = blockIdx.x;
    int vlen = valid_len[b];
    int ntiles = (vlen + 63) >> 6;

    // load Q tile (pre-scaled by 1/sqrt(D) = 1/16)
    const float* qg = g_q + (size_t)(b*TT + ttile*64) * DD;
    for (int s = 0; s < 64; s++)
        Qs[s*QS_STRIDE + tid] = qg[s*DD + tid] * 0.0625f;
    if (tid < 64) { mrow[tid] = -INFINITY; lrow[tid] = 0.f; }

    float o[4][16];
    #pragma unroll
    for (int j = 0; j < 4; j++)
        #pragma unroll
        for (int i = 0; i < 16; i++) o[j][i] = 0.f;

    const float* kg = g_k + (size_t)b*NKEY*DD;
    const float* vg = g_v + (size_t)b*NKEY*DD;

    for (int nt = 0; nt < ntiles; nt++) {
        __syncthreads();                       // KV free (prev PV done), Ss free
        for (int s = 0; s < 64; s++)
            KV[s*QS_STRIDE + tid] = kg[(nt*64 + s)*DD + tid];
        __syncthreads();

        // S = Q . K^T  (thread: rows ty*4+j, cols i*16+tx)
        float sacc[4][4];
        #pragma unroll
        for (int j = 0; j < 4; j++)
            #pragma unroll
            for (int i = 0; i < 4; i++) sacc[j][i] = 0.f;
        #pragma unroll 4
        for (int k = 0; k < 256; k++) {
            float a[4], bb[4];
            #pragma unroll
            for (int j = 0; j < 4; j++) a[j] = Qs[(ty*4+j)*QS_STRIDE + k];
            #pragma unroll
            for (int i = 0; i < 4; i++) bb[i] = KV[(i*16+tx)*QS_STRIDE + k];
            #pragma unroll
            for (int j = 0; j < 4; j++)
                #pragma unroll
                for (int i = 0; i < 4; i++)
                    sacc[j][i] += a[j]*bb[i];
        }
        #pragma unroll
        for (int j = 0; j < 4; j++)
            #pragma unroll
            for (int i = 0; i < 4; i++) {
                int nc = i*16 + tx;
                float v = sacc[j][i];
                if (nt*64 + nc >= vlen) v = -1e30f;
                Ss[(ty*4+j)*SS_STRIDE + nc] = v;
            }
        __syncthreads();

        // load V tile into KV (K no longer needed)
        for (int s = 0; s < 64; s++)
            KV[s*QS_STRIDE + tid] = vg[(nt*64 + s)*DD + tid];

        // online softmax per row (threads 0..63)
        if (tid < 64) {
            float mold = mrow[tid];
            float mx = mold;
            #pragma unroll 8
            for (int n = 0; n < 64; n++) mx = fmaxf(mx, Ss[tid*SS_STRIDE + n]);
            float c = __expf(mold - mx);
            float lsum = 0.f;
            #pragma unroll 8
            for (int n = 0; n < 64; n++) {
                float p = __expf(Ss[tid*SS_STRIDE + n] - mx);
                Ss[tid*SS_STRIDE + n] = p;
                lsum += p;
            }
            mrow[tid] = mx;
            lrow[tid] = lrow[tid]*c + lsum;
            crow[tid] = c;
        }
        __syncthreads();

        // rescale accumulators, then O += P @ V
        #pragma unroll
        for (int j = 0; j < 4; j++) {
            float c = crow[ty*4+j];
            #pragma unroll
            for (int i = 0; i < 16; i++) o[j][i] *= c;
        }
        #pragma unroll 2
        for (int n = 0; n < 64; n++) {
            float p[4], vv[16];
            #pragma unroll
            for (int j = 0; j < 4; j++) p[j] = Ss[(ty*4+j)*SS_STRIDE + n];
            #pragma unroll
            for (int i = 0; i < 16; i++) vv[i] = KV[n*QS_STRIDE + i*16 + tx];
            #pragma unroll
            for (int j = 0; j < 4; j++)
                #pragma unroll
                for (int i = 0; i < 16; i++)
                    o[j][i] += p[j]*vv[i];
        }
    }

    // finalize: divide by l, column-max over this thread's 4 rows
    float cm[16];
    #pragma unroll
    for (int i = 0; i < 16; i++) cm[i] = -INFINITY;
    #pragma unroll
    for (int j = 0; j < 4; j++) {
        float inv = 1.f / lrow[ty*4+j];
        #pragma unroll
        for (int i = 0; i < 16; i++)
            cm[i] = fmaxf(cm[i], o[j][i]*inv);
    }
    __syncthreads();                           // done reading Ss/KV; reuse Ss as [16][256]
    #pragma unroll
    for (int i = 0; i < 16; i++)
        Ss[ty*256 + i*16 + tx] = cm[i];
    __syncthreads();
    {
        int col = tid;
        float m = Ss[col];
        #pragma unroll
        for (int y = 1; y < 16; y++) m = fmaxf(m, Ss[y*256 + col]);
        g_pmax[(b*8 + ttile)*DD + col] = m;
    }
}

// ---------------------------------------------------------------------------
// K4: out[b] = sigmoid( (max_tiles(pmax) + le) . w_out + b_out )
// ---------------------------------------------------------------------------
__global__ void k_final(const int* __restrict__ labels, const float* __restrict__ emb,
                        const float* __restrict__ w_out, const float* __restrict__ b_out,
                        float* __restrict__ out) {
    int b = blockIdx.x, d = threadIdx.x;
    float m = g_pmax[(b*8 + 0)*DD + d];
    #pragma unroll
    for (int j = 1; j < 8; j++) m = fmaxf(m, g_pmax[(b*8 + j)*DD + d]);
    float val = (m + emb[labels[b]*DD + d]) * w_out[d];
    #pragma unroll
    for (int o = 16; o; o >>= 1) val += __shfl_down_sync(0xFFFFFFFFu, val, o);
    __shared__ float ws[8];
    if ((d & 31) == 0) ws[d >> 5] = val;
    __syncthreads();
    if (d == 0) {
        float s = 0.f;
        #pragma unroll
        for (int i = 0; i < 8; i++) s += ws[i];
        s += b_out[0];
        out[b] = 1.f / (1.f + expf(-s));
    }
}

// ---------------------------------------------------------------------------
extern "C" void kernel_launch(void* const* d_in, const int* in_sizes, int n_in,
                              void* d_out, int out_size) {
    const float* traj      = (const float*)d_in[0];
    const int*   labels    = (const int*)  d_in[1];
    const float* h         = (const float*)d_in[2];
    const int*   valid_len = (const int*)  d_in[3];
    const float* emb       = (const float*)d_in[4];
    const float* w_mlp     = (const float*)d_in[5];
    const float* b_mlp     = (const float*)d_in[6];
    const float* ln_g      = (const float*)d_in[7];
    const float* ln_b      = (const float*)d_in[8];
    const float* wq        = (const float*)d_in[9];
    const float* bq        = (const float*)d_in[10];
    const float* wk        = (const float*)d_in[11];
    const float* bk        = (const float*)d_in[12];
    const float* wv        = (const float*)d_in[13];
    const float* bv        = (const float*)d_in[14];
    const float* w_out     = (const float*)d_in[15];
    const float* b_out     = (const float*)d_in[16];
    float* out = (float*)d_out;

    cudaFuncSetAttribute(k_attn, cudaFuncAttributeMaxDynamicSharedMemorySize, ATTN_SMEM);

    k_build_x<<<dim3(TT, BB), DD>>>(traj, labels, emb, w_mlp, b_mlp, ln_g, ln_b);
    k_qkv<<<dim3(256, 2, 3), 256>>>(h, wq, bq, wk, bk, wv, bv);
    k_attn<<<dim3(8, BB), 256, ATTN_SMEM>>>(valid_len);
    k_final<<<BB, DD>>>(labels, emb, w_out, b_out, out);
}

// round 3
// speedup vs baseline: 1.9091x; 1.9091x over previous
#include <cuda_runtime.h>
#include <math.h>
#include <stdint.h>

#define BB 64
#define TT 512
#define NKEY 512
#define DD 256

// Scratch (device globals: allocation-free per harness rules)
__device__ float g_x[BB*TT*DD];
__device__ float g_q[BB*TT*DD];
__device__ float g_k[BB*NKEY*DD];
__device__ float g_v[BB*NKEY*DD];
__device__ float g_pmax[BB*8*DD];
__device__ float g_wTf[3*DD*DD];   // transposed weights [z][n][k], tf32-rounded fp32

// ---------------------------------------------------------------------------
// tf32 helpers (base PTX ISA, valid on sm_100 target)
// ---------------------------------------------------------------------------
__device__ __forceinline__ float f2tf32f(float x) {
    uint32_t r;
    asm("cvt.rna.tf32.f32 %0, %1;" : "=r"(r) : "f"(x));
    return __uint_as_float(r);
}
__device__ __forceinline__ uint32_t fu(float x) { return __float_as_uint(x); }

// D += A(m16xk8, row) * B(k8xn8, col) ; all tf32 in b32 regs, fp32 accum
__device__ __forceinline__ void mma_tf32(float* d, const uint32_t* a,
                                         uint32_t b0, uint32_t b1) {
    asm volatile(
        "mma.sync.aligned.m16n8k8.row.col.f32.tf32.tf32.f32 "
        "{%0,%1,%2,%3}, {%4,%5,%6,%7}, {%8,%9}, {%0,%1,%2,%3};"
        : "+f"(d[0]), "+f"(d[1]), "+f"(d[2]), "+f"(d[3])
        : "r"(a[0]), "r"(a[1]), "r"(a[2]), "r"(a[3]), "r"(b0), "r"(b1));
}

// ---------------------------------------------------------------------------
// K1: x = leaky_relu(LN(traj @ w_mlp + b_mlp)) + emb[labels]   -> g_x [B,T,D]
// ---------------------------------------------------------------------------
__global__ void k_build_x(const float* __restrict__ traj, const int* __restrict__ labels,
                          const float* __restrict__ emb, const float* __restrict__ w_mlp,
                          const float* __restrict__ b_mlp, const float* __restrict__ ln_g,
                          const float* __restrict__ ln_b) {
    int b = blockIdx.y, t = blockIdx.x, d = threadIdx.x;
    int row = b*TT + t;
    float t0 = traj[row*2 + 0];
    float t1 = traj[row*2 + 1];
    float v = t0*w_mlp[d] + t1*w_mlp[DD + d] + b_mlp[d];

    float s = v, s2 = v*v;
    #pragma unroll
    for (int o = 16; o; o >>= 1) {
        s  += __shfl_down_sync(0xFFFFFFFFu, s,  o);
        s2 += __shfl_down_sync(0xFFFFFFFFu, s2, o);
    }
    __shared__ float ws[8], ws2[8];
    __shared__ float smu, srs;
    int lane = d & 31, w = d >> 5;
    if (lane == 0) { ws[w] = s; ws2[w] = s2; }
    __syncthreads();
    if (d == 0) {
        float a = 0.f, a2 = 0.f;
        #pragma unroll
        for (int i = 0; i < 8; i++) { a += ws[i]; a2 += ws2[i]; }
        float mu  = a  * (1.f/DD);
        float var = a2 * (1.f/DD) - mu*mu;
        smu = mu;
        srs = rsqrtf(var + 1e-5f);
    }
    __syncthreads();
    float y = (v - smu) * srs * ln_g[d] + ln_b[d];
    y = (y >= 0.f) ? y : 0.01f * y;
    y += emb[labels[b]*DD + d];
    g_x[row*DD + d] = y;
}

// ---------------------------------------------------------------------------
// K1b: transpose weights -> g_wTf[z][n][k] = tf32(W_z[k][n])
// ---------------------------------------------------------------------------
__global__ void k_wt(const float* __restrict__ wq, const float* __restrict__ wk,
                     const float* __restrict__ wv) {
    int z = blockIdx.y;
    const float* W = (z == 0) ? wq : (z == 1) ? wk : wv;
    __shared__ float s[32*257];
    int tid = threadIdx.x;
    int k0 = blockIdx.x * 32;
    #pragma unroll
    for (int i = 0; i < 32; i++) {
        int f = tid + i*256;
        int k = f >> 8, n = f & 255;
        s[k*257 + n] = W[(k0 + k)*DD + n];
    }
    __syncthreads();
    int n = tid;
    float* dst = &g_wTf[z*DD*DD + n*DD + k0];
    #pragma unroll
    for (int j = 0; j < 32; j++)
        dst[j] = f2tf32f(s[j*257 + n]);
}

// ---------------------------------------------------------------------------
// K2: tf32 mma GEMM: Out = A @ W + bias. Block tile 128x128, K-chunk 32.
// 8 warps: wm (wid&3) -> 32 rows, wn (wid>>2) -> 64 cols. m16n8k8 frags.
// grid (256 m-tiles, 2 n-halves, 3 matrices), 256 threads.
// ---------------------------------------------------------------------------
__global__ __launch_bounds__(256) void k_qkv_tc(const float* __restrict__ h,
        const float* __restrict__ bq, const float* __restrict__ bk,
        const float* __restrict__ bv) {
    __shared__ float As[128*36];   // stride 36: (4r+c)%32 distinct for frag loads
    __shared__ float Bs[128*36];

    int tid = threadIdx.x;
    int wid = tid >> 5, lane = tid & 31;
    int g = lane >> 2, t = lane & 3;
    int wm = wid & 3, wn = wid >> 2;
    int z = blockIdx.z;
    int m0 = blockIdx.x * 128;
    int nb0 = blockIdx.y * 128;

    const float* Asrc = (z == 0) ? g_x : h;
    const float* Wt = g_wTf + z*DD*DD;
    const float* bias = (z == 0) ? bq : (z == 1) ? bk : bv;
    float* Out = (z == 0) ? g_q : (z == 1) ? g_k : g_v;

    float acc[2][8][4];
    #pragma unroll
    for (int mf = 0; mf < 2; mf++)
        #pragma unroll
        for (int nf = 0; nf < 8; nf++)
            #pragma unroll
            for (int i = 0; i < 4; i++) acc[mf][nf][i] = 0.f;

    for (int kc = 0; kc < 8; kc++) {
        int k0 = kc * 32;
        __syncthreads();
        #pragma unroll
        for (int i = 0; i < 4; i++) {
            int f = tid + i*256;
            int row = f >> 3, q4 = (f & 7)*4;
            float4 a4 = *(const float4*)&Asrc[(size_t)(m0+row)*DD + k0 + q4];
            As[row*36 + q4+0] = f2tf32f(a4.x);
            As[row*36 + q4+1] = f2tf32f(a4.y);
            As[row*36 + q4+2] = f2tf32f(a4.z);
            As[row*36 + q4+3] = f2tf32f(a4.w);
            float4 b4 = *(const float4*)&Wt[(size_t)(nb0+row)*DD + k0 + q4];
            Bs[row*36 + q4+0] = b4.x;
            Bs[row*36 + q4+1] = b4.y;
            Bs[row*36 + q4+2] = b4.z;
            Bs[row*36 + q4+3] = b4.w;
        }
        __syncthreads();

        #pragma unroll
        for (int kk = 0; kk < 4; kk++) {
            int kb = kk * 8;
            uint32_t a[2][4];
            #pragma unroll
            for (int mf = 0; mf < 2; mf++) {
                const float* ar = As + (wm*32 + mf*16 + g)*36 + kb;
                a[mf][0] = fu(ar[t]);
                a[mf][1] = fu(ar[8*36 + t]);
                a[mf][2] = fu(ar[t + 4]);
                a[mf][3] = fu(ar[8*36 + t + 4]);
            }
            #pragma unroll
            for (int nf = 0; nf < 8; nf++) {
                const float* br = Bs + (wn*64 + nf*8 + g)*36 + kb;
                uint32_t b0 = fu(br[t]);
                uint32_t b1 = fu(br[t + 4]);
                mma_tf32(acc[0][nf], a[0], b0, b1);
                mma_tf32(acc[1][nf], a[1], b0, b1);
            }
        }
    }

    // epilogue: bias fused, float2 stores
    #pragma unroll
    for (int mf = 0; mf < 2; mf++) {
        int r0 = m0 + wm*32 + mf*16 + g;
        #pragma unroll
        for (int nf = 0; nf < 8; nf++) {
            int col = nb0 + wn*64 + nf*8 + t*2;
            float bb0 = bias[col], bb1 = bias[col+1];
            *(float2*)&Out[(size_t)r0*DD + col] =
                make_float2(acc[mf][nf][0] + bb0, acc[mf][nf][1] + bb1);
            *(float2*)&Out[(size_t)(r0+8)*DD + col] =
                make_float2(acc[mf][nf][2] + bb0, acc[mf][nf][3] + bb1);
        }
    }
}

// ---------------------------------------------------------------------------
// K3: tf32 mma flash attention + fused per-tile max pool.
// Block: 64 t-rows, 8 warps (wm: 16 rows, wn: half of cols). Grid (8, 64).
// Smem floats: Qs[64][260] Ks[64][260] Vt[256][67] Ss[64][68] + m/l/c rows.
// ---------------------------------------------------------------------------
#define QS_OFF 0
#define KS_OFF 16640
#define VT_OFF 33280
#define SS_OFF 50432
#define MR_OFF 54784
#define LR_OFF 54848
#define CR_OFF 54912
#define ATTN_SMEM (54976*4)

__global__ __launch_bounds__(256, 1) void k_attn_tc(const int* __restrict__ valid_len) {
    extern __shared__ float sm[];
    float* Qs   = sm + QS_OFF;   // [64][260]
    float* Ks   = sm + KS_OFF;   // [64][260]  (reused as O staging at the end)
    float* Vt   = sm + VT_OFF;   // [256][67]  V^T
    float* Ss   = sm + SS_OFF;   // [64][68]
    float* mrow = sm + MR_OFF;
    float* lrow = sm + LR_OFF;
    float* crow = sm + CR_OFF;

    int tid = threadIdx.x;
    int wid = tid >> 5, lane = tid & 31;
    int g = lane >> 2, t = lane & 3;
    int wm = wid & 3, wn = wid >> 2;
    int b = blockIdx.y, ttile = blockIdx.x;
    int vlen = valid_len[b];
    int ntiles = (vlen + 63) >> 6;
    int r0 = wm*16 + g;                      // this thread's S/O rows: r0, r0+8

    // prologue: load Q tile (scaled by 1/16, tf32-rounded)
    const float* qg = g_q + (size_t)(b*TT + ttile*64)*DD;
    #pragma unroll
    for (int i = 0; i < 16; i++) {
        int f = tid + i*256;
        int row = f >> 6, c4 = (f & 63)*4;
        float4 v = *(const float4*)&qg[(size_t)row*DD + c4];
        Qs[row*260 + c4+0] = f2tf32f(v.x * 0.0625f);
        Qs[row*260 + c4+1] = f2tf32f(v.y * 0.0625f);
        Qs[row*260 + c4+2] = f2tf32f(v.z * 0.0625f);
        Qs[row*260 + c4+3] = f2tf32f(v.w * 0.0625f);
    }
    if (tid < 64) { mrow[tid] = -INFINITY; lrow[tid] = 0.f; }

    float accO[16][4];
    #pragma unroll
    for (int nf = 0; nf < 16; nf++)
        #pragma unroll
        for (int i = 0; i < 4; i++) accO[nf][i] = 0.f;

    const float* kg = g_k + (size_t)b*NKEY*DD;
    const float* vg = g_v + (size_t)b*NKEY*DD;

    for (int nt = 0; nt < ntiles; nt++) {
        int n0 = nt * 64;
        __syncthreads();   // prev PV done with Ss/Vt; Qs ready on first iter

        // K tile [64][256] fp32->tf32
        #pragma unroll
        for (int i = 0; i < 16; i++) {
            int f = tid + i*256;
            int row = f >> 6, c4 = (f & 63)*4;
            float4 v = *(const float4*)&kg[(size_t)(n0+row)*DD + c4];
            Ks[row*260 + c4+0] = f2tf32f(v.x);
            Ks[row*260 + c4+1] = f2tf32f(v.y);
            Ks[row*260 + c4+2] = f2tf32f(v.z);
            Ks[row*260 + c4+3] = f2tf32f(v.w);
        }
        // V^T tile: thread owns column d = tid; stride 67 -> conflict-free frag loads
        {
            const float* vp = vg + (size_t)n0*DD + tid;
            float* vt = Vt + tid*67;
            #pragma unroll 8
            for (int s = 0; s < 64; s++)
                vt[s] = f2tf32f(vp[(size_t)s*DD]);
        }
        __syncthreads();

        // S = Q . K^T  (warp: 16 rows x 32 cols, 4 n-frags)
        float sacc[4][4];
        #pragma unroll
        for (int nf = 0; nf < 4; nf++)
            #pragma unroll
            for (int i = 0; i < 4; i++) sacc[nf][i] = 0.f;

        #pragma unroll 8
        for (int ks = 0; ks < 32; ks++) {
            int kb = ks * 8;
            uint32_t a[4];
            const float* qr = Qs + r0*260 + kb;
            a[0] = fu(qr[t]);
            a[1] = fu(qr[8*260 + t]);
            a[2] = fu(qr[t + 4]);
            a[3] = fu(qr[8*260 + t + 4]);
            #pragma unroll
            for (int nf = 0; nf < 4; nf++) {
                const float* kr = Ks + (wn*32 + nf*8 + g)*260 + kb;
                mma_tf32(sacc[nf], a, fu(kr[t]), fu(kr[t+4]));
            }
        }
        #pragma unroll
        for (int nf = 0; nf < 4; nf++) {
            int col = wn*32 + nf*8 + t*2;
            *(float2*)&Ss[r0*68 + col]     = make_float2(sacc[nf][0], sacc[nf][1]);
            *(float2*)&Ss[(r0+8)*68 + col] = make_float2(sacc[nf][2], sacc[nf][3]);
        }
        __syncthreads();

        // online softmax per row (threads 0..63); P stored tf32-rounded
        if (tid < 64) {
            int row = tid;
            int nvalid = vlen - n0; if (nvalid > 64) nvalid = 64;
            float mold = mrow[row];
            float mx = mold;
            for (int n = 0; n < nvalid; n++) mx = fmaxf(mx, Ss[row*68 + n]);
            float c = __expf(mold - mx);
            float lsum = 0.f;
            #pragma unroll 8
            for (int n = 0; n < 64; n++) {
                float p = (n < nvalid) ? __expf(Ss[row*68 + n] - mx) : 0.f;
                Ss[row*68 + n] = f2tf32f(p);
                lsum += p;
            }
            mrow[row] = mx;
            lrow[row] = lrow[row]*c + lsum;
            crow[row] = c;
        }
        __syncthreads();

        // rescale O, then O += P @ V   (warp: 16 rows x 128 cols, 16 n-frags)
        float c0 = crow[r0], c1 = crow[r0+8];
        #pragma unroll
        for (int nf = 0; nf < 16; nf++) {
            accO[nf][0] *= c0; accO[nf][1] *= c0;
            accO[nf][2] *= c1; accO[nf][3] *= c1;
        }
        #pragma unroll
        for (int ks = 0; ks < 8; ks++) {
            int kb = ks * 8;
            uint32_t a[4];
            const float* pr = Ss + r0*68 + kb;
            a[0] = fu(pr[t]);
            a[1] = fu(pr[8*68 + t]);
            a[2] = fu(pr[t + 4]);
            a[3] = fu(pr[8*68 + t + 4]);
            #pragma unroll
            for (int nf = 0; nf < 16; nf++) {
                const float* vr = Vt + (wn*128 + nf*8 + g)*67 + kb;
                mma_tf32(accO[nf], a, fu(vr[t]), fu(vr[t+4]));
            }
        }
    }

    // finalize: /l, stage O into Ks region, column-max, write g_pmax
    float inv0 = 1.f / lrow[r0], inv1 = 1.f / lrow[r0+8];
    float* Os = Ks;
    #pragma unroll
    for (int nf = 0; nf < 16; nf++) {
        int col = wn*128 + nf*8 + t*2;
        *(float2*)&Os[r0*260 + col] =
            make_float2(accO[nf][0]*inv0, accO[nf][1]*inv0);
        *(float2*)&Os[(r0+8)*260 + col] =
            make_float2(accO[nf][2]*inv1, accO[nf][3]*inv1);
    }
    __syncthreads();
    {
        int col = tid;
        float m = Os[col];
        #pragma unroll 8
        for (int r = 1; r < 64; r++) m = fmaxf(m, Os[r*260 + col]);
        g_pmax[(size_t)(b*8 + ttile)*DD + col] = m;
    }
}

// ---------------------------------------------------------------------------
// K4: out[b] = sigmoid( (max_tiles(pmax) + le) . w_out + b_out )
// ---------------------------------------------------------------------------
__global__ void k_final(const int* __restrict__ labels, const float* __restrict__ emb,
                        const float* __restrict__ w_out, const float* __restrict__ b_out,
                        float* __restrict__ out) {
    int b = blockIdx.x, d = threadIdx.x;
    float m = g_pmax[(b*8 + 0)*DD + d];
    #pragma unroll
    for (int j = 1; j < 8; j++) m = fmaxf(m, g_pmax[(b*8 + j)*DD + d]);
    float val = (m + emb[labels[b]*DD + d]) * w_out[d];
    #pragma unroll
    for (int o = 16; o; o >>= 1) val += __shfl_down_sync(0xFFFFFFFFu, val, o);
    __shared__ float ws[8];
    if ((d & 31) == 0) ws[d >> 5] = val;
    __syncthreads();
    if (d == 0) {
        float s = 0.f;
        #pragma unroll
        for (int i = 0; i < 8; i++) s += ws[i];
        s += b_out[0];
        out[b] = 1.f / (1.f + expf(-s));
    }
}

// ---------------------------------------------------------------------------
extern "C" void kernel_launch(void* const* d_in, const int* in_sizes, int n_in,
                              void* d_out, int out_size) {
    const float* traj      = (const float*)d_in[0];
    const int*   labels    = (const int*)  d_in[1];
    const float* h         = (const float*)d_in[2];
    const int*   valid_len = (const int*)  d_in[3];
    const float* emb       = (const float*)d_in[4];
    const float* w_mlp     = (const float*)d_in[5];
    const float* b_mlp     = (const float*)d_in[6];
    const float* ln_g      = (const float*)d_in[7];
    const float* ln_b      = (const float*)d_in[8];
    const float* wq        = (const float*)d_in[9];
    const float* bq        = (const float*)d_in[10];
    const float* wk        = (const float*)d_in[11];
    const float* bk        = (const float*)d_in[12];
    const float* wv        = (const float*)d_in[13];
    const float* bv        = (const float*)d_in[14];
    const float* w_out     = (const float*)d_in[15];
    const float* b_out     = (const float*)d_in[16];
    float* out = (float*)d_out;

    cudaFuncSetAttribute(k_attn_tc, cudaFuncAttributeMaxDynamicSharedMemorySize, ATTN_SMEM);

    k_build_x<<<dim3(TT, BB), DD>>>(traj, labels, emb, w_mlp, b_mlp, ln_g, ln_b);
    k_wt<<<dim3(8, 3), 256>>>(wq, wk, wv);
    k_qkv_tc<<<dim3(256, 2, 3), 256>>>(h, bq, bk, bv);
    k_attn_tc<<<dim3(8, BB), 256, ATTN_SMEM>>>(valid_len);
    k_final<<<BB, DD>>>(labels, emb, w_out, b_out, out);
}

// round 4
// speedup vs baseline: 4.0638x; 2.1286x over previous
#include <cuda_runtime.h>
#include <cuda_bf16.h>
#include <math.h>
#include <stdint.h>

#define BB 64
#define TT 512
#define NKEY 512
#define DD 256

// Scratch (device globals: allocation-free per harness rules)
__device__ __nv_bfloat16 g_xb[BB*TT*DD];
__device__ __nv_bfloat16 g_qb[BB*TT*DD];
__device__ __nv_bfloat16 g_kb[BB*NKEY*DD];
__device__ __nv_bfloat16 g_vb[BB*NKEY*DD];
__device__ __nv_bfloat16 g_wTb[3*DD*DD];   // transposed weights [z][n][k], bf16
__device__ float g_pmax[BB*8*DD];

// ---------------------------------------------------------------------------
// helpers (base PTX ISA, valid on sm_100 target)
// ---------------------------------------------------------------------------
__device__ __forceinline__ uint32_t smem_u32(const void* p) {
    uint32_t a;
    asm("{ .reg .u64 t; cvta.to.shared.u64 t, %1; cvt.u32.u64 %0, t; }" : "=r"(a) : "l"(p));
    return a;
}
__device__ __forceinline__ void mma_bf16(float* d, const uint32_t* a, uint32_t b0, uint32_t b1) {
    asm volatile(
        "mma.sync.aligned.m16n8k16.row.col.f32.bf16.bf16.f32 "
        "{%0,%1,%2,%3}, {%4,%5,%6,%7}, {%8,%9}, {%0,%1,%2,%3};"
        : "+f"(d[0]), "+f"(d[1]), "+f"(d[2]), "+f"(d[3])
        : "r"(a[0]), "r"(a[1]), "r"(a[2]), "r"(a[3]), "r"(b0), "r"(b1));
}
__device__ __forceinline__ void ldm_x4(uint32_t* r, uint32_t addr) {
    asm volatile("ldmatrix.sync.aligned.m8n8.x4.shared.b16 {%0,%1,%2,%3}, [%4];"
        : "=r"(r[0]), "=r"(r[1]), "=r"(r[2]), "=r"(r[3]) : "r"(addr));
}
__device__ __forceinline__ void ldm_x4_t(uint32_t* r, uint32_t addr) {
    asm volatile("ldmatrix.sync.aligned.m8n8.x4.trans.shared.b16 {%0,%1,%2,%3}, [%4];"
        : "=r"(r[0]), "=r"(r[1]), "=r"(r[2]), "=r"(r[3]) : "r"(addr));
}
__device__ __forceinline__ void cp_async16(uint32_t dst, const void* src) {
    asm volatile("cp.async.cg.shared.global [%0], [%1], 16;" :: "r"(dst), "l"(src));
}
#define CP_COMMIT() asm volatile("cp.async.commit_group;" ::: "memory")
#define CP_WAIT(n)  asm volatile("cp.async.wait_group %0;" :: "n"(n) : "memory")

// ---------------------------------------------------------------------------
// K1: x = leaky_relu(LN(traj @ w_mlp + b_mlp)) + emb[labels] -> g_xb (bf16)
// ---------------------------------------------------------------------------
__global__ void k_build_x(const float* __restrict__ traj, const int* __restrict__ labels,
                          const float* __restrict__ emb, const float* __restrict__ w_mlp,
                          const float* __restrict__ b_mlp, const float* __restrict__ ln_g,
                          const float* __restrict__ ln_b) {
    int b = blockIdx.y, t = blockIdx.x, d = threadIdx.x;
    int row = b*TT + t;
    float t0 = traj[row*2 + 0];
    float t1 = traj[row*2 + 1];
    float v = t0*w_mlp[d] + t1*w_mlp[DD + d] + b_mlp[d];

    float s = v, s2 = v*v;
    #pragma unroll
    for (int o = 16; o; o >>= 1) {
        s  += __shfl_down_sync(0xFFFFFFFFu, s,  o);
        s2 += __shfl_down_sync(0xFFFFFFFFu, s2, o);
    }
    __shared__ float ws[8], ws2[8];
    __shared__ float smu, srs;
    int lane = d & 31, w = d >> 5;
    if (lane == 0) { ws[w] = s; ws2[w] = s2; }
    __syncthreads();
    if (d == 0) {
        float a = 0.f, a2 = 0.f;
        #pragma unroll
        for (int i = 0; i < 8; i++) { a += ws[i]; a2 += ws2[i]; }
        float mu  = a  * (1.f/DD);
        float var = a2 * (1.f/DD) - mu*mu;
        smu = mu;
        srs = rsqrtf(var + 1e-5f);
    }
    __syncthreads();
    float y = (v - smu) * srs * ln_g[d] + ln_b[d];
    y = (y >= 0.f) ? y : 0.01f * y;
    y += emb[labels[b]*DD + d];
    g_xb[(size_t)row*DD + d] = __float2bfloat16(y);
}

// ---------------------------------------------------------------------------
// K1b: transpose weights -> g_wTb[z][n][k] = bf16(W_z[k][n])
// ---------------------------------------------------------------------------
__global__ void k_wt(const float* __restrict__ wq, const float* __restrict__ wk,
                     const float* __restrict__ wv) {
    int z = blockIdx.y;
    const float* W = (z == 0) ? wq : (z == 1) ? wk : wv;
    __shared__ float s[32*257];
    int tid = threadIdx.x;
    int k0 = blockIdx.x * 32;
    #pragma unroll
    for (int i = 0; i < 32; i++) {
        int f = tid + i*256;
        int k = f >> 8, n = f & 255;
        s[k*257 + n] = W[(k0 + k)*DD + n];
    }
    __syncthreads();
    int n = tid;
    __nv_bfloat16* dst = &g_wTb[(size_t)z*DD*DD + (size_t)n*DD + k0];
    #pragma unroll
    for (int j = 0; j < 32; j++)
        dst[j] = __float2bfloat16(s[j*257 + n]);
}

// ---------------------------------------------------------------------------
// K2: bf16 mma GEMM: Out = A @ W + bias -> bf16. Tile 128x128, K-chunk 64.
// 8 warps: wm (wid&3) 32 rows x wn (wid>>2) 64 cols; m16n8k16 + ldmatrix.
// ---------------------------------------------------------------------------
#define GS 36   // chunk row stride in uint32 (64 bf16 = 32U + 4 pad; 36%32==4)

__global__ __launch_bounds__(256) void k_qkv_tc(const float* __restrict__ h,
        const float* __restrict__ bq, const float* __restrict__ bk,
        const float* __restrict__ bv) {
    __shared__ uint32_t As[128*GS];
    __shared__ uint32_t Bs[128*GS];

    int tid = threadIdx.x;
    int wid = tid >> 5, lane = tid & 31;
    int g = lane >> 2, t = lane & 3;
    int wm = wid & 3, wn = wid >> 2;
    int l7 = lane & 7, lh = (lane >> 3) & 1, lq = lane >> 4;
    int z = blockIdx.z;
    int m0 = blockIdx.x * 128;
    int n0 = blockIdx.y * 128;

    const __nv_bfloat16* WT = g_wTb + (size_t)z*DD*DD;
    const float* bias = (z == 0) ? bq : (z == 1) ? bk : bv;
    __nv_bfloat16* Out = (z == 0) ? g_qb : (z == 1) ? g_kb : g_vb;

    uint32_t asb = smem_u32(As), bsb = smem_u32(Bs);

    float acc[2][8][4];
    #pragma unroll
    for (int mf = 0; mf < 2; mf++)
        #pragma unroll
        for (int nf = 0; nf < 8; nf++)
            #pragma unroll
            for (int i = 0; i < 4; i++) acc[mf][nf][i] = 0.f;

    for (int kc = 0; kc < 4; kc++) {
        int k0 = kc * 64;
        __syncthreads();
        // B tile: 128 n-rows x 64 k bf16 (raw copy)
        #pragma unroll
        for (int i = 0; i < 4; i++) {
            int f = tid + i*256;
            int r = f >> 3, cu = (f & 7) * 4;
            uint4 v = *(const uint4*)&WT[(size_t)(n0 + r)*DD + k0 + cu*2];
            *(uint4*)&Bs[r*GS + cu] = v;
        }
        // A tile
        if (z == 0) {
            #pragma unroll
            for (int i = 0; i < 4; i++) {
                int f = tid + i*256;
                int r = f >> 3, cu = (f & 7) * 4;
                uint4 v = *(const uint4*)&g_xb[(size_t)(m0 + r)*DD + k0 + cu*2];
                *(uint4*)&As[r*GS + cu] = v;
            }
        } else {
            #pragma unroll
            for (int i = 0; i < 8; i++) {
                int f = tid + i*256;
                int r = f >> 4, c4 = (f & 15) * 4;
                float4 v = *(const float4*)&h[(size_t)(m0 + r)*DD + k0 + c4];
                __nv_bfloat162 p0 = __floats2bfloat162_rn(v.x, v.y);
                __nv_bfloat162 p1 = __floats2bfloat162_rn(v.z, v.w);
                As[r*GS + (c4 >> 1)]     = *(uint32_t*)&p0;
                As[r*GS + (c4 >> 1) + 1] = *(uint32_t*)&p1;
            }
        }
        __syncthreads();

        #pragma unroll
        for (int s = 0; s < 4; s++) {
            uint32_t a[2][4];
            #pragma unroll
            for (int mf = 0; mf < 2; mf++) {
                int row = wm*32 + mf*16 + l7 + lh*8;
                ldm_x4(a[mf], asb + (uint32_t)(row*GS + s*8 + lq*4)*4);
            }
            #pragma unroll
            for (int np = 0; np < 4; np++) {
                uint32_t b[4];
                int row = wn*64 + np*16 + lq*8 + l7;
                ldm_x4(b, bsb + (uint32_t)(row*GS + s*8 + lh*4)*4);
                mma_bf16(acc[0][np*2],   a[0], b[0], b[1]);
                mma_bf16(acc[1][np*2],   a[1], b[0], b[1]);
                mma_bf16(acc[0][np*2+1], a[0], b[2], b[3]);
                mma_bf16(acc[1][np*2+1], a[1], b[2], b[3]);
            }
        }
    }

    // epilogue: +bias, bf16x2 stores
    #pragma unroll
    for (int mf = 0; mf < 2; mf++) {
        int r = m0 + wm*32 + mf*16 + g;
        #pragma unroll
        for (int nf = 0; nf < 8; nf++) {
            int col = n0 + wn*64 + nf*8 + 2*t;
            float b0 = bias[col], b1 = bias[col+1];
            __nv_bfloat162 v0 = __floats2bfloat162_rn(acc[mf][nf][0]+b0, acc[mf][nf][1]+b1);
            __nv_bfloat162 v1 = __floats2bfloat162_rn(acc[mf][nf][2]+b0, acc[mf][nf][3]+b1);
            *(uint32_t*)&Out[(size_t)r*DD + col]     = *(uint32_t*)&v0;
            *(uint32_t*)&Out[(size_t)(r+8)*DD + col] = *(uint32_t*)&v1;
        }
    }
}

// ---------------------------------------------------------------------------
// K3: bf16 mma flash attention + fused max pool. 512 threads / 16 warps.
// cp.async double-buffered K/V tiles, ldmatrix frags, all-thread softmax.
// Smem (uint32 units): Q[64][132] K0 K1 V0 V1 Ss[64][68] m/l/c
// ---------------------------------------------------------------------------
#define TSU 132            // Q/K/V row stride in uint32 (128U + 4 pad)
#define QS_U 0
#define K0_U 8448
#define K1_U 16896
#define V0_U 25344
#define V1_U 33792
#define SS_U 42240
#define MR_U 46592
#define LR_U 46656
#define CR_U 46720
#define ATTN_SMEM (46784*4)

// copy one 64x256 bf16 tile (row-major) into smem at stride TSU, via cp.async
__device__ __forceinline__ void tile_cp(uint32_t dst_base, const __nv_bfloat16* src, int tid) {
    #pragma unroll
    for (int i = 0; i < 4; i++) {
        int c = tid + i*512;
        int r = c >> 5, o = c & 31;
        cp_async16(dst_base + (uint32_t)(r*TSU + o*4)*4, src + (size_t)r*DD + o*8);
    }
}

__global__ __launch_bounds__(512, 1) void k_attn_tc(const int* __restrict__ valid_len) {
    extern __shared__ uint32_t smu[];
    uint32_t base = smem_u32(smu);
    float* Ssf  = (float*)(smu + SS_U);
    float* mrow = (float*)(smu + MR_U);
    float* lrow = (float*)(smu + LR_U);
    float* crow = (float*)(smu + CR_U);

    int tid = threadIdx.x;
    int wid = tid >> 5, lane = tid & 31;
    int g = lane >> 2, t = lane & 3;
    int l7 = lane & 7, lh = (lane >> 3) & 1, lq = lane >> 4;
    int wm = wid >> 2, wn = wid & 3;       // wm: 16-row group; wn: col group
    int b = blockIdx.y, ttile = blockIdx.x;
    int vlen = valid_len[b];
    int ntiles = (vlen + 63) >> 6;
    int r0 = wm*16 + g;

    const __nv_bfloat16* qg = g_qb + (size_t)(b*TT + ttile*64)*DD;
    const __nv_bfloat16* kg = g_kb + (size_t)b*NKEY*DD;
    const __nv_bfloat16* vg = g_vb + (size_t)b*NKEY*DD;

    // prologue: Q + tile0 K/V in one async group
    tile_cp(base + QS_U*4, qg, tid);
    tile_cp(base + K0_U*4, kg, tid);
    tile_cp(base + V0_U*4, vg, tid);
    CP_COMMIT();
    if (tid < 64) { mrow[tid] = -INFINITY; lrow[tid] = 0.f; }

    float accO[8][4];
    #pragma unroll
    for (int nf = 0; nf < 8; nf++)
        #pragma unroll
        for (int i = 0; i < 4; i++) accO[nf][i] = 0.f;

    for (int nt = 0; nt < ntiles; nt++) {
        int n0 = nt * 64;
        int buf = nt & 1;
        uint32_t KB = base + (buf ? K1_U : K0_U)*4;
        uint32_t VB = base + (buf ? V1_U : V0_U)*4;
        __syncthreads();                    // prior-iter reads of buf^1 done
        if (nt + 1 < ntiles) {
            uint32_t KN = base + (buf ? K0_U : K1_U)*4;
            uint32_t VN = base + (buf ? V0_U : V1_U)*4;
            tile_cp(KN, kg + (size_t)(n0 + 64)*DD, tid);
            tile_cp(VN, vg + (size_t)(n0 + 64)*DD, tid);
            CP_COMMIT();
            CP_WAIT(1);
        } else {
            CP_WAIT(0);
        }
        __syncthreads();                    // tile nt visible

        // S = Q.K^T : warp tile 16 rows x 16 cols (2 nf), 16 k16 steps
        float sacc[2][4];
        #pragma unroll
        for (int nf = 0; nf < 2; nf++)
            #pragma unroll
            for (int i = 0; i < 4; i++) sacc[nf][i] = 0.f;
        #pragma unroll 4
        for (int s = 0; s < 16; s++) {
            uint32_t a[4], bfr[4];
            int arow = wm*16 + l7 + lh*8;
            ldm_x4(a, base + (uint32_t)(QS_U + arow*TSU + s*8 + lq*4)*4);
            int brow = wn*16 + lq*8 + l7;
            ldm_x4(bfr, KB + (uint32_t)(brow*TSU + s*8 + lh*4)*4);
            mma_bf16(sacc[0], a, bfr[0], bfr[1]);
            mma_bf16(sacc[1], a, bfr[2], bfr[3]);
        }
        #pragma unroll
        for (int nf = 0; nf < 2; nf++) {
            int c = wn*16 + nf*8 + 2*t;
            *(float2*)&Ssf[r0*68 + c] =
                make_float2(sacc[nf][0]*0.0625f, sacc[nf][1]*0.0625f);
            *(float2*)&Ssf[(r0+8)*68 + c] =
                make_float2(sacc[nf][2]*0.0625f, sacc[nf][3]*0.0625f);
        }
        __syncthreads();

        // softmax: all 512 threads; row = tid>>3, 8 cols each; P overwrites S (bf16)
        {
            int row = tid >> 3, sub = tid & 7;
            int nv = vlen - n0; if (nv > 64) nv = 64;
            float sv[8];
            #pragma unroll
            for (int j = 0; j < 8; j++) {
                int col = sub*8 + j;
                sv[j] = (col < nv) ? Ssf[row*68 + col] : -INFINITY;
            }
            float mx = sv[0];
            #pragma unroll
            for (int j = 1; j < 8; j++) mx = fmaxf(mx, sv[j]);
            #pragma unroll
            for (int o = 1; o < 8; o <<= 1)
                mx = fmaxf(mx, __shfl_xor_sync(0xFFFFFFFFu, mx, o));
            float mold = mrow[row];
            mx = fmaxf(mx, mold);
            float psum = 0.f;
            uint32_t pp[4];
            #pragma unroll
            for (int j = 0; j < 4; j++) {
                float p0 = __expf(sv[2*j]   - mx);
                float p1 = __expf(sv[2*j+1] - mx);
                if (sub*8 + 2*j   >= nv) p0 = 0.f;
                if (sub*8 + 2*j+1 >= nv) p1 = 0.f;
                psum += p0 + p1;
                __nv_bfloat162 pk = __floats2bfloat162_rn(p0, p1);
                pp[j] = *(uint32_t*)&pk;
            }
            #pragma unroll
            for (int o = 1; o < 8; o <<= 1)
                psum += __shfl_xor_sync(0xFFFFFFFFu, psum, o);
            uint32_t* Pu = smu + SS_U + row*68 + sub*4;
            Pu[0] = pp[0]; Pu[1] = pp[1]; Pu[2] = pp[2]; Pu[3] = pp[3];
            if (sub == 0) {
                float c = __expf(mold - mx);
                mrow[row] = mx;
                lrow[row] = lrow[row]*c + psum;
                crow[row] = c;
            }
        }
        __syncthreads();

        // O rescale + O += P.V : warp tile 16 rows x 64 d-cols (8 nf), 4 k16 steps
        float c0 = crow[r0], c1 = crow[r0+8];
        #pragma unroll
        for (int nf = 0; nf < 8; nf++) {
            accO[nf][0] *= c0; accO[nf][1] *= c0;
            accO[nf][2] *= c1; accO[nf][3] *= c1;
        }
        #pragma unroll
        for (int ks = 0; ks < 4; ks++) {
            uint32_t a[4];
            int arow = wm*16 + l7 + lh*8;
            ldm_x4(a, base + (uint32_t)(SS_U + arow*68 + ks*8 + lq*4)*4);
            #pragma unroll
            for (int np = 0; np < 4; np++) {
                uint32_t bfr[4];
                int krow = ks*16 + lh*8 + l7;
                int du = wn*32 + np*8 + lq*4;     // d-col/2
                ldm_x4_t(bfr, VB + (uint32_t)(krow*TSU + du)*4);
                mma_bf16(accO[np*2],   a, bfr[0], bfr[1]);
                mma_bf16(accO[np*2+1], a, bfr[2], bfr[3]);
            }
        }
    }

    // finalize: /l, stage O (fp32) over K0+K1 region, column max -> g_pmax
    __syncthreads();
    float* Os = (float*)(smu + K0_U);            // [64][260]
    float inv0 = 1.f / lrow[r0], inv1 = 1.f / lrow[r0+8];
    #pragma unroll
    for (int nf = 0; nf < 8; nf++) {
        int c = wn*64 + nf*8 + 2*t;
        *(float2*)&Os[r0*260 + c] = make_float2(accO[nf][0]*inv0, accO[nf][1]*inv0);
        *(float2*)&Os[(r0+8)*260 + c] = make_float2(accO[nf][2]*inv1, accO[nf][3]*inv1);
    }
    __syncthreads();
    if (tid < 256) {
        int col = tid;
        float m = Os[col];
        #pragma unroll 8
        for (int r = 1; r < 64; r++) m = fmaxf(m, Os[r*260 + col]);
        g_pmax[(size_t)(b*8 + ttile)*DD + col] = m;
    }
}

// ---------------------------------------------------------------------------
// K4: out[b] = sigmoid( (max_tiles(pmax) + le) . w_out + b_out )
// ---------------------------------------------------------------------------
__global__ void k_final(const int* __restrict__ labels, const float* __restrict__ emb,
                        const float* __restrict__ w_out, const float* __restrict__ b_out,
                        float* __restrict__ out) {
    int b = blockIdx.x, d = threadIdx.x;
    float m = g_pmax[(b*8 + 0)*DD + d];
    #pragma unroll
    for (int j = 1; j < 8; j++) m = fmaxf(m, g_pmax[(b*8 + j)*DD + d]);
    float val = (m + emb[labels[b]*DD + d]) * w_out[d];
    #pragma unroll
    for (int o = 16; o; o >>= 1) val += __shfl_down_sync(0xFFFFFFFFu, val, o);
    __shared__ float ws[8];
    if ((d & 31) == 0) ws[d >> 5] = val;
    __syncthreads();
    if (d == 0) {
        float s = 0.f;
        #pragma unroll
        for (int i = 0; i < 8; i++) s += ws[i];
        s += b_out[0];
        out[b] = 1.f / (1.f + expf(-s));
    }
}

// ---------------------------------------------------------------------------
extern "C" void kernel_launch(void* const* d_in, const int* in_sizes, int n_in,
                              void* d_out, int out_size) {
    const float* traj      = (const float*)d_in[0];
    const int*   labels    = (const int*)  d_in[1];
    const float* h         = (const float*)d_in[2];
    const int*   valid_len = (const int*)  d_in[3];
    const float* emb       = (const float*)d_in[4];
    const float* w_mlp     = (const float*)d_in[5];
    const float* b_mlp     = (const float*)d_in[6];
    const float* ln_g      = (const float*)d_in[7];
    const float* ln_b      = (const float*)d_in[8];
    const float* wq        = (const float*)d_in[9];
    const float* bq        = (const float*)d_in[10];
    const float* wk        = (const float*)d_in[11];
    const float* bk        = (const float*)d_in[12];
    const float* wv        = (const float*)d_in[13];
    const float* bv        = (const float*)d_in[14];
    const float* w_out     = (const float*)d_in[15];
    const float* b_out     = (const float*)d_in[16];
    float* out = (float*)d_out;

    cudaFuncSetAttribute(k_attn_tc, cudaFuncAttributeMaxDynamicSharedMemorySize, ATTN_SMEM);

    k_build_x<<<dim3(TT, BB), DD>>>(traj, labels, emb, w_mlp, b_mlp, ln_g, ln_b);
    k_wt<<<dim3(8, 3), 256>>>(wq, wk, wv);
    k_qkv_tc<<<dim3(256, 2, 3), 256>>>(h, bq, bk, bv);
    k_attn_tc<<<dim3(8, BB), 512, ATTN_SMEM>>>(valid_len);
    k_final<<<BB, DD>>>(labels, emb, w_out, b_out, out);
}

// round 5
// speedup vs baseline: 4.7073x; 1.1583x over previous
#include <cuda_runtime.h>
#include <cuda_bf16.h>
#include <math.h>
#include <stdint.h>

#define BB 64
#define TT 512
#define NKEY 512
#define DD 256

// Scratch (device globals: allocation-free per harness rules)
__device__ __nv_bfloat16 g_xb[BB*TT*DD];
__device__ __nv_bfloat16 g_hb[BB*NKEY*DD];
__device__ __nv_bfloat16 g_qb[BB*TT*DD];
__device__ __nv_bfloat16 g_kb[BB*NKEY*DD];
__device__ __nv_bfloat16 g_vb[BB*NKEY*DD];
__device__ __nv_bfloat16 g_wTb[3*DD*DD];   // transposed weights [z][n][k], bf16
__device__ float g_pmax[BB*8*DD];

// ---------------------------------------------------------------------------
// helpers (base PTX ISA, valid on sm_100 target)
// ---------------------------------------------------------------------------
__device__ __forceinline__ uint32_t smem_u32(const void* p) {
    uint32_t a;
    asm("{ .reg .u64 t; cvta.to.shared.u64 t, %1; cvt.u32.u64 %0, t; }" : "=r"(a) : "l"(p));
    return a;
}
__device__ __forceinline__ void mma_bf16(float* d, const uint32_t* a, uint32_t b0, uint32_t b1) {
    asm volatile(
        "mma.sync.aligned.m16n8k16.row.col.f32.bf16.bf16.f32 "
        "{%0,%1,%2,%3}, {%4,%5,%6,%7}, {%8,%9}, {%0,%1,%2,%3};"
        : "+f"(d[0]), "+f"(d[1]), "+f"(d[2]), "+f"(d[3])
        : "r"(a[0]), "r"(a[1]), "r"(a[2]), "r"(a[3]), "r"(b0), "r"(b1));
}
__device__ __forceinline__ void ldm_x4(uint32_t* r, uint32_t addr) {
    asm volatile("ldmatrix.sync.aligned.m8n8.x4.shared.b16 {%0,%1,%2,%3}, [%4];"
        : "=r"(r[0]), "=r"(r[1]), "=r"(r[2]), "=r"(r[3]) : "r"(addr));
}
__device__ __forceinline__ void ldm_x4_t(uint32_t* r, uint32_t addr) {
    asm volatile("ldmatrix.sync.aligned.m8n8.x4.trans.shared.b16 {%0,%1,%2,%3}, [%4];"
        : "=r"(r[0]), "=r"(r[1]), "=r"(r[2]), "=r"(r[3]) : "r"(addr));
}
__device__ __forceinline__ void cp_async16(uint32_t dst, const void* src) {
    asm volatile("cp.async.cg.shared.global [%0], [%1], 16;" :: "r"(dst), "l"(src));
}
#define CP_COMMIT() asm volatile("cp.async.commit_group;" ::: "memory")
#define CP_WAIT(n)  asm volatile("cp.async.wait_group %0;" :: "n"(n) : "memory")

// ---------------------------------------------------------------------------
// K0: convert h (fp32) -> g_hb (bf16). 8.4M elems, float4-vectorized.
// ---------------------------------------------------------------------------
__global__ void k_prep(const float* __restrict__ h) {
    size_t i = (size_t)blockIdx.x * 256 + threadIdx.x;    // over 2.1M float4
    float4 v = *(const float4*)&h[i*4];
    __nv_bfloat162 p0 = __floats2bfloat162_rn(v.x, v.y);
    __nv_bfloat162 p1 = __floats2bfloat162_rn(v.z, v.w);
    uint32_t* dst = (uint32_t*)&g_hb[i*4];
    dst[0] = *(uint32_t*)&p0;
    dst[1] = *(uint32_t*)&p1;
}

// ---------------------------------------------------------------------------
// K1: x = leaky_relu(LN(traj @ w_mlp + b_mlp)) + emb[labels] -> g_xb (bf16)
// warp-per-row, shuffle-only reduce, zero barriers. grid 4096 x 256 thr.
// ---------------------------------------------------------------------------
__global__ void k_build_x(const float* __restrict__ traj, const int* __restrict__ labels,
                          const float* __restrict__ emb, const float* __restrict__ w_mlp,
                          const float* __restrict__ b_mlp, const float* __restrict__ ln_g,
                          const float* __restrict__ ln_b) {
    int warp = threadIdx.x >> 5, lane = threadIdx.x & 31;
    int row = blockIdx.x*8 + warp;          // row = b*TT + t
    int b = row >> 9;
    float t0 = traj[row*2 + 0];
    float t1 = traj[row*2 + 1];
    int lab = labels[b];

    float v[8];
    float s = 0.f, s2 = 0.f;
    #pragma unroll
    for (int j = 0; j < 8; j++) {
        int d = lane + 32*j;
        v[j] = t0*w_mlp[d] + t1*w_mlp[DD + d] + b_mlp[d];
        s += v[j]; s2 += v[j]*v[j];
    }
    #pragma unroll
    for (int o = 16; o; o >>= 1) {
        s  += __shfl_xor_sync(0xFFFFFFFFu, s,  o);
        s2 += __shfl_xor_sync(0xFFFFFFFFu, s2, o);
    }
    float mu  = s  * (1.f/DD);
    float var = s2 * (1.f/DD) - mu*mu;
    float rs  = rsqrtf(var + 1e-5f);

    __nv_bfloat16* dst = g_xb + (size_t)row*DD;
    #pragma unroll
    for (int j = 0; j < 8; j++) {
        int d = lane + 32*j;
        float y = (v[j] - mu) * rs * ln_g[d] + ln_b[d];
        y = (y >= 0.f) ? y : 0.01f * y;
        y += emb[lab*DD + d];
        dst[d] = __float2bfloat16(y);
    }
}

// ---------------------------------------------------------------------------
// K1b: transpose weights -> g_wTb[z][n][k] = bf16(W_z[k][n])
// ---------------------------------------------------------------------------
__global__ void k_wt(const float* __restrict__ wq, const float* __restrict__ wk,
                     const float* __restrict__ wv) {
    int z = blockIdx.y;
    const float* W = (z == 0) ? wq : (z == 1) ? wk : wv;
    __shared__ float s[32*257];
    int tid = threadIdx.x;
    int k0 = blockIdx.x * 32;
    #pragma unroll
    for (int i = 0; i < 32; i++) {
        int f = tid + i*256;
        int k = f >> 8, n = f & 255;
        s[k*257 + n] = W[(k0 + k)*DD + n];
    }
    __syncthreads();
    int n = tid;
    __nv_bfloat16* dst = &g_wTb[(size_t)z*DD*DD + (size_t)n*DD + k0];
    #pragma unroll
    for (int j = 0; j < 32; j++)
        dst[j] = __float2bfloat16(s[j*257 + n]);
}

// ---------------------------------------------------------------------------
// K2: bf16 mma GEMM with cp.async double-buffered K-chunks.
// blockIdx.y: 0,1 -> q n-tiles; 2,3 -> k; 4,5 -> v. A = g_xb (q) or g_hb.
// Tile 128x128, K-chunk 64, 8 warps, m16n8k16 + ldmatrix. q scaled 1/16.
// ---------------------------------------------------------------------------
#define GS 36   // chunk row stride in uint32 (64 bf16 = 32U + 4 pad; 36%32==4)
#define QKV_BUF (2*128*GS)                 // one double-buffer half (A+B), u32
#define QKV_SMEM (2*QKV_BUF*4)             // 73728 bytes

__global__ __launch_bounds__(256) void k_qkv_tc(const float* __restrict__ bq,
        const float* __restrict__ bk, const float* __restrict__ bv) {
    extern __shared__ uint32_t qsm[];
    uint32_t base = smem_u32(qsm);

    int tid = threadIdx.x;
    int wid = tid >> 5, lane = tid & 31;
    int g = lane >> 2, t = lane & 3;
    int wm = wid & 3, wn = wid >> 2;
    int l7 = lane & 7, lh = (lane >> 3) & 1, lq = lane >> 4;
    int y = blockIdx.y;
    int z = y >> 1;
    int m0 = blockIdx.x * 128;
    int n0 = (y & 1) * 128;

    const __nv_bfloat16* A  = (z == 0) ? g_xb : g_hb;
    const __nv_bfloat16* WT = g_wTb + (size_t)z*DD*DD;
    const float* bias = (z == 0) ? bq : (z == 1) ? bk : bv;
    __nv_bfloat16* Out = (z == 0) ? g_qb : (z == 1) ? g_kb : g_vb;
    float oscale = (z == 0) ? 0.0625f : 1.f;

    // fill chunk kc into buffer buf (A rows m0.., B rows n0..)
    auto fill = [&](int buf, int kc) {
        uint32_t ab = base + (uint32_t)buf*QKV_BUF*4;
        uint32_t bb = ab + 128*GS*4;
        int k0 = kc * 64;
        #pragma unroll
        for (int i = 0; i < 4; i++) {
            int f = tid + i*256;
            int r = f >> 3, cu = (f & 7) * 4;
            cp_async16(ab + (uint32_t)(r*GS + cu)*4, A  + (size_t)(m0 + r)*DD + k0 + cu*2);
            cp_async16(bb + (uint32_t)(r*GS + cu)*4, WT + (size_t)(n0 + r)*DD + k0 + cu*2);
        }
    };

    float acc[2][8][4];
    #pragma unroll
    for (int mf = 0; mf < 2; mf++)
        #pragma unroll
        for (int nf = 0; nf < 8; nf++)
            #pragma unroll
            for (int i = 0; i < 4; i++) acc[mf][nf][i] = 0.f;

    fill(0, 0);
    CP_COMMIT();

    for (int kc = 0; kc < 4; kc++) {
        int buf = kc & 1;
        if (kc < 3) { fill(buf ^ 1, kc + 1); CP_COMMIT(); CP_WAIT(1); }
        else        { CP_WAIT(0); }
        __syncthreads();

        uint32_t asb = base + (uint32_t)buf*QKV_BUF*4;
        uint32_t bsb = asb + 128*GS*4;
        #pragma unroll
        for (int s = 0; s < 4; s++) {
            uint32_t a[2][4];
            #pragma unroll
            for (int mf = 0; mf < 2; mf++) {
                int row = wm*32 + mf*16 + l7 + lh*8;
                ldm_x4(a[mf], asb + (uint32_t)(row*GS + s*8 + lq*4)*4);
            }
            #pragma unroll
            for (int np = 0; np < 4; np++) {
                uint32_t b[4];
                int row = wn*64 + np*16 + lq*8 + l7;
                ldm_x4(b, bsb + (uint32_t)(row*GS + s*8 + lh*4)*4);
                mma_bf16(acc[0][np*2],   a[0], b[0], b[1]);
                mma_bf16(acc[1][np*2],   a[1], b[0], b[1]);
                mma_bf16(acc[0][np*2+1], a[0], b[2], b[3]);
                mma_bf16(acc[1][np*2+1], a[1], b[2], b[3]);
            }
        }
        __syncthreads();
    }

    // epilogue: (+bias) * oscale, bf16x2 stores
    #pragma unroll
    for (int mf = 0; mf < 2; mf++) {
        int r = m0 + wm*32 + mf*16 + g;
        #pragma unroll
        for (int nf = 0; nf < 8; nf++) {
            int col = n0 + wn*64 + nf*8 + 2*t;
            float b0 = bias[col], b1 = bias[col+1];
            __nv_bfloat162 v0 = __floats2bfloat162_rn((acc[mf][nf][0]+b0)*oscale,
                                                      (acc[mf][nf][1]+b1)*oscale);
            __nv_bfloat162 v1 = __floats2bfloat162_rn((acc[mf][nf][2]+b0)*oscale,
                                                      (acc[mf][nf][3]+b1)*oscale);
            *(uint32_t*)&Out[(size_t)r*DD + col]     = *(uint32_t*)&v0;
            *(uint32_t*)&Out[(size_t)(r+8)*DD + col] = *(uint32_t*)&v1;
        }
    }
}

// ---------------------------------------------------------------------------
// K3: bf16 mma flash attention + fused max pool. 512 threads / 16 warps.
// cp.async double-buffered K/V tiles, ldmatrix frags, all-thread softmax.
// ---------------------------------------------------------------------------
#define TSU 132            // Q/K/V row stride in uint32 (128U + 4 pad)
#define QS_U 0
#define K0_U 8448
#define K1_U 16896
#define V0_U 25344
#define V1_U 33792
#define SS_U 42240
#define MR_U 46592
#define LR_U 46656
#define CR_U 46720
#define ATTN_SMEM (46784*4)

__device__ __forceinline__ void tile_cp(uint32_t dst_base, const __nv_bfloat16* src, int tid) {
    #pragma unroll
    for (int i = 0; i < 4; i++) {
        int c = tid + i*512;
        int r = c >> 5, o = c & 31;
        cp_async16(dst_base + (uint32_t)(r*TSU + o*4)*4, src + (size_t)r*DD + o*8);
    }
}

__global__ __launch_bounds__(512, 1) void k_attn_tc(const int* __restrict__ valid_len) {
    extern __shared__ uint32_t smu[];
    uint32_t base = smem_u32(smu);
    float* Ssf  = (float*)(smu + SS_U);
    float* mrow = (float*)(smu + MR_U);
    float* lrow = (float*)(smu + LR_U);
    float* crow = (float*)(smu + CR_U);

    int tid = threadIdx.x;
    int wid = tid >> 5, lane = tid & 31;
    int g = lane >> 2, t = lane & 3;
    int l7 = lane & 7, lh = (lane >> 3) & 1, lq = lane >> 4;
    int wm = wid >> 2, wn = wid & 3;
    int b = blockIdx.y, ttile = blockIdx.x;
    int vlen = valid_len[b];
    int ntiles = (vlen + 63) >> 6;
    int r0 = wm*16 + g;

    const __nv_bfloat16* qg = g_qb + (size_t)(b*TT + ttile*64)*DD;
    const __nv_bfloat16* kg = g_kb + (size_t)b*NKEY*DD;
    const __nv_bfloat16* vg = g_vb + (size_t)b*NKEY*DD;

    tile_cp(base + QS_U*4, qg, tid);
    tile_cp(base + K0_U*4, kg, tid);
    tile_cp(base + V0_U*4, vg, tid);
    CP_COMMIT();
    if (tid < 64) { mrow[tid] = -INFINITY; lrow[tid] = 0.f; }

    float accO[8][4];
    #pragma unroll
    for (int nf = 0; nf < 8; nf++)
        #pragma unroll
        for (int i = 0; i < 4; i++) accO[nf][i] = 0.f;

    for (int nt = 0; nt < ntiles; nt++) {
        int n0 = nt * 64;
        int buf = nt & 1;
        uint32_t KB = base + (buf ? K1_U : K0_U)*4;
        uint32_t VB = base + (buf ? V1_U : V0_U)*4;
        __syncthreads();
        if (nt + 1 < ntiles) {
            uint32_t KN = base + (buf ? K0_U : K1_U)*4;
            uint32_t VN = base + (buf ? V0_U : V1_U)*4;
            tile_cp(KN, kg + (size_t)(n0 + 64)*DD, tid);
            tile_cp(VN, vg + (size_t)(n0 + 64)*DD, tid);
            CP_COMMIT();
            CP_WAIT(1);
        } else {
            CP_WAIT(0);
        }
        __syncthreads();

        // S = Q.K^T (q pre-scaled by 1/16)
        float sacc[2][4];
        #pragma unroll
        for (int nf = 0; nf < 2; nf++)
            #pragma unroll
            for (int i = 0; i < 4; i++) sacc[nf][i] = 0.f;
        #pragma unroll 4
        for (int s = 0; s < 16; s++) {
            uint32_t a[4], bfr[4];
            int arow = wm*16 + l7 + lh*8;
            ldm_x4(a, base + (uint32_t)(QS_U + arow*TSU + s*8 + lq*4)*4);
            int brow = wn*16 + lq*8 + l7;
            ldm_x4(bfr, KB + (uint32_t)(brow*TSU + s*8 + lh*4)*4);
            mma_bf16(sacc[0], a, bfr[0], bfr[1]);
            mma_bf16(sacc[1], a, bfr[2], bfr[3]);
        }
        #pragma unroll
        for (int nf = 0; nf < 2; nf++) {
            int c = wn*16 + nf*8 + 2*t;
            *(float2*)&Ssf[r0*68 + c]     = make_float2(sacc[nf][0], sacc[nf][1]);
            *(float2*)&Ssf[(r0+8)*68 + c] = make_float2(sacc[nf][2], sacc[nf][3]);
        }
        __syncthreads();

        // softmax: row = tid>>3, 8 cols per thread; P overwrites S (bf16)
        {
            int row = tid >> 3, sub = tid & 7;
            int nv = vlen - n0; if (nv > 64) nv = 64;
            float sv[8];
            #pragma unroll
            for (int j = 0; j < 8; j++) {
                int col = sub*8 + j;
                sv[j] = (col < nv) ? Ssf[row*68 + col] : -INFINITY;
            }
            float mx = sv[0];
            #pragma unroll
            for (int j = 1; j < 8; j++) mx = fmaxf(mx, sv[j]);
            #pragma unroll
            for (int o = 1; o < 8; o <<= 1)
                mx = fmaxf(mx, __shfl_xor_sync(0xFFFFFFFFu, mx, o));
            float mold = mrow[row];
            mx = fmaxf(mx, mold);
            float psum = 0.f;
            uint32_t pp[4];
            #pragma unroll
            for (int j = 0; j < 4; j++) {
                float p0 = __expf(sv[2*j]   - mx);
                float p1 = __expf(sv[2*j+1] - mx);
                if (sub*8 + 2*j   >= nv) p0 = 0.f;
                if (sub*8 + 2*j+1 >= nv) p1 = 0.f;
                psum += p0 + p1;
                __nv_bfloat162 pk = __floats2bfloat162_rn(p0, p1);
                pp[j] = *(uint32_t*)&pk;
            }
            #pragma unroll
            for (int o = 1; o < 8; o <<= 1)
                psum += __shfl_xor_sync(0xFFFFFFFFu, psum, o);
            uint32_t* Pu = smu + SS_U + row*68 + sub*4;
            Pu[0] = pp[0]; Pu[1] = pp[1]; Pu[2] = pp[2]; Pu[3] = pp[3];
            if (sub == 0) {
                float c = __expf(mold - mx);
                mrow[row] = mx;
                lrow[row] = lrow[row]*c + psum;
                crow[row] = c;
            }
        }
        __syncthreads();

        // O rescale + O += P.V
        float c0 = crow[r0], c1 = crow[r0+8];
        #pragma unroll
        for (int nf = 0; nf < 8; nf++) {
            accO[nf][0] *= c0; accO[nf][1] *= c0;
            accO[nf][2] *= c1; accO[nf][3] *= c1;
        }
        #pragma unroll
        for (int ks = 0; ks < 4; ks++) {
            uint32_t a[4];
            int arow = wm*16 + l7 + lh*8;
            ldm_x4(a, base + (uint32_t)(SS_U + arow*68 + ks*8 + lq*4)*4);
            #pragma unroll
            for (int np = 0; np < 4; np++) {
                uint32_t bfr[4];
                int krow = ks*16 + lh*8 + l7;
                int du = wn*32 + np*8 + lq*4;
                ldm_x4_t(bfr, VB + (uint32_t)(krow*TSU + du)*4);
                mma_bf16(accO[np*2],   a, bfr[0], bfr[1]);
                mma_bf16(accO[np*2+1], a, bfr[2], bfr[3]);
            }
        }
    }

    // finalize: /l, stage O (fp32), column max -> g_pmax
    __syncthreads();
    float* Os = (float*)(smu + K0_U);            // [64][260]
    float inv0 = 1.f / lrow[r0], inv1 = 1.f / lrow[r0+8];
    #pragma unroll
    for (int nf = 0; nf < 8; nf++) {
        int c = wn*64 + nf*8 + 2*t;
        *(float2*)&Os[r0*260 + c] = make_float2(accO[nf][0]*inv0, accO[nf][1]*inv0);
        *(float2*)&Os[(r0+8)*260 + c] = make_float2(accO[nf][2]*inv1, accO[nf][3]*inv1);
    }
    __syncthreads();
    if (tid < 256) {
        int col = tid;
        float m = Os[col];
        #pragma unroll 8
        for (int r = 1; r < 64; r++) m = fmaxf(m, Os[r*260 + col]);
        g_pmax[(size_t)(b*8 + ttile)*DD + col] = m;
    }
}

// ---------------------------------------------------------------------------
// K4: out[b] = sigmoid( (max_tiles(pmax) + le) . w_out + b_out )
// ---------------------------------------------------------------------------
__global__ void k_final(const int* __restrict__ labels, const float* __restrict__ emb,
                        const float* __restrict__ w_out, const float* __restrict__ b_out,
                        float* __restrict__ out) {
    int b = blockIdx.x, d = threadIdx.x;
    float m = g_pmax[(b*8 + 0)*DD + d];
    #pragma unroll
    for (int j = 1; j < 8; j++) m = fmaxf(m, g_pmax[(b*8 + j)*DD + d]);
    float val = (m + emb[labels[b]*DD + d]) * w_out[d];
    #pragma unroll
    for (int o = 16; o; o >>= 1) val += __shfl_down_sync(0xFFFFFFFFu, val, o);
    __shared__ float ws[8];
    if ((d & 31) == 0) ws[d >> 5] = val;
    __syncthreads();
    if (d == 0) {
        float s = 0.f;
        #pragma unroll
        for (int i = 0; i < 8; i++) s += ws[i];
        s += b_out[0];
        out[b] = 1.f / (1.f + expf(-s));
    }
}

// ---------------------------------------------------------------------------
extern "C" void kernel_launch(void* const* d_in, const int* in_sizes, int n_in,
                              void* d_out, int out_size) {
    const float* traj      = (const float*)d_in[0];
    const int*   labels    = (const int*)  d_in[1];
    const float* h         = (const float*)d_in[2];
    const int*   valid_len = (const int*)  d_in[3];
    const float* emb       = (const float*)d_in[4];
    const float* w_mlp     = (const float*)d_in[5];
    const float* b_mlp     = (const float*)d_in[6];
    const float* ln_g      = (const float*)d_in[7];
    const float* ln_b      = (const float*)d_in[8];
    const float* wq        = (const float*)d_in[9];
    const float* bq        = (const float*)d_in[10];
    const float* wk        = (const float*)d_in[11];
    const float* bk        = (const float*)d_in[12];
    const float* wv        = (const float*)d_in[13];
    const float* bv        = (const float*)d_in[14];
    const float* w_out     = (const float*)d_in[15];
    const float* b_out     = (const float*)d_in[16];
    float* out = (float*)d_out;

    cudaFuncSetAttribute(k_attn_tc, cudaFuncAttributeMaxDynamicSharedMemorySize, ATTN_SMEM);
    cudaFuncSetAttribute(k_qkv_tc,  cudaFuncAttributeMaxDynamicSharedMemorySize, QKV_SMEM);

    k_prep<<<BB*NKEY*DD/4/256, 256>>>(h);
    k_build_x<<<BB*TT/8, 256>>>(traj, labels, emb, w_mlp, b_mlp, ln_g, ln_b);
    k_wt<<<dim3(8, 3), 256>>>(wq, wk, wv);
    k_qkv_tc<<<dim3(256, 6), 256, QKV_SMEM>>>(bq, bk, bv);
    k_attn_tc<<<dim3(8, BB), 512, ATTN_SMEM>>>(valid_len);
    k_final<<<BB, DD>>>(labels, emb, w_out, b_out, out);
}